// round 1
// baseline (speedup 1.0000x reference)
#include <cuda_runtime.h>
#include <math.h>

// Problem constants
#define BB 16
#define SS 2048
#define EE 768
#define HH 8
#define DH 96
#define MM (BB*SS)          // 32768 rows

// Scratch (device globals: allocation-free rule)
__device__ float g_qkv[(size_t)MM * 2304];   // 302 MB
__device__ float g_ctx[(size_t)MM * 768];    // 100 MB
__device__ float g_att[(size_t)MM * 768];    // 100 MB
__device__ float g_h  [(size_t)MM * 384];    //  50 MB

// ---------------------------------------------------------------------------
// Tiled SGEMM:  C[M x N] = A[M x K] @ B[N x K]^T + bias,  optional ReLU.
// M = 32768 (fixed multiple of 128); N in {2304,768,384}; K = 768.
// All dims are multiples of tile sizes -> no bounds checks.
// ---------------------------------------------------------------------------
template<int RELU>
__global__ __launch_bounds__(256, 2)
void gemm_nt(const float* __restrict__ A, const float* __restrict__ Bm,
             const float* __restrict__ bias, float* __restrict__ C,
             int N, int K) {
    constexpr int BMt = 128, BNt = 128, BKt = 16, TM = 8, TN = 8;
    __shared__ __align__(16) float As[BKt][BMt];
    __shared__ __align__(16) float Bs[BKt][BNt];

    const int tid = threadIdx.x;              // 256 threads
    const int tx  = tid & 15;                 // 0..15
    const int ty  = tid >> 4;                 // 0..15
    const int m0  = blockIdx.y * BMt;
    const int n0  = blockIdx.x * BNt;

    float acc[TM][TN];
#pragma unroll
    for (int i = 0; i < TM; i++)
#pragma unroll
        for (int j = 0; j < TN; j++) acc[i][j] = 0.0f;

    for (int k0 = 0; k0 < K; k0 += BKt) {
        // Load A tile (128 rows x 16 k) as 512 float4, 2 per thread.
#pragma unroll
        for (int i = 0; i < 2; i++) {
            int f   = tid + i * 256;
            int row = f >> 2;
            int kc  = (f & 3) << 2;
            float4 v = *(const float4*)(A + (size_t)(m0 + row) * K + k0 + kc);
            As[kc + 0][row] = v.x; As[kc + 1][row] = v.y;
            As[kc + 2][row] = v.z; As[kc + 3][row] = v.w;
        }
        // Load B tile (128 rows x 16 k), same pattern.
#pragma unroll
        for (int i = 0; i < 2; i++) {
            int f   = tid + i * 256;
            int row = f >> 2;
            int kc  = (f & 3) << 2;
            float4 v = *(const float4*)(Bm + (size_t)(n0 + row) * K + k0 + kc);
            Bs[kc + 0][row] = v.x; Bs[kc + 1][row] = v.y;
            Bs[kc + 2][row] = v.z; Bs[kc + 3][row] = v.w;
        }
        __syncthreads();

#pragma unroll
        for (int kk = 0; kk < BKt; kk++) {
            float4 a0 = *(const float4*)&As[kk][ty * TM];
            float4 a1 = *(const float4*)&As[kk][ty * TM + 4];
            float4 b0 = *(const float4*)&Bs[kk][tx * TN];
            float4 b1 = *(const float4*)&Bs[kk][tx * TN + 4];
            float a[TM] = {a0.x,a0.y,a0.z,a0.w,a1.x,a1.y,a1.z,a1.w};
            float b[TN] = {b0.x,b0.y,b0.z,b0.w,b1.x,b1.y,b1.z,b1.w};
#pragma unroll
            for (int i = 0; i < TM; i++)
#pragma unroll
                for (int j = 0; j < TN; j++)
                    acc[i][j] = fmaf(a[i], b[j], acc[i][j]);
        }
        __syncthreads();
    }

    // Epilogue: bias (+ReLU), float4 stores.
    float bj[TN];
#pragma unroll
    for (int j = 0; j < TN; j++) bj[j] = bias[n0 + tx * TN + j];

#pragma unroll
    for (int i = 0; i < TM; i++) {
        float4 o0, o1;
        float v0 = acc[i][0] + bj[0], v1 = acc[i][1] + bj[1];
        float v2 = acc[i][2] + bj[2], v3 = acc[i][3] + bj[3];
        float v4 = acc[i][4] + bj[4], v5 = acc[i][5] + bj[5];
        float v6 = acc[i][6] + bj[6], v7 = acc[i][7] + bj[7];
        if (RELU) {
            v0 = fmaxf(v0, 0.f); v1 = fmaxf(v1, 0.f); v2 = fmaxf(v2, 0.f); v3 = fmaxf(v3, 0.f);
            v4 = fmaxf(v4, 0.f); v5 = fmaxf(v5, 0.f); v6 = fmaxf(v6, 0.f); v7 = fmaxf(v7, 0.f);
        }
        o0 = make_float4(v0, v1, v2, v3);
        o1 = make_float4(v4, v5, v6, v7);
        float* crow = C + (size_t)(m0 + ty * TM + i) * N + n0 + tx * TN;
        *(float4*)(crow)     = o0;
        *(float4*)(crow + 4) = o1;
    }
}

// ---------------------------------------------------------------------------
// Attention over axis-0 (length 16) per (s, h): 16x16 scores over Dh=96.
// grid = (S, H), 128 threads.
// ---------------------------------------------------------------------------
__global__ __launch_bounds__(128)
void attn_kernel() {
    const int s = blockIdx.x;
    const int h = blockIdx.y;
    const int tid = threadIdx.x;

    __shared__ float q[16][96];
    __shared__ float k[16][96];
    __shared__ float v[16][96];
    __shared__ float sc[16][17];

    const float* base = g_qkv + (size_t)s * 2304 + h * DH;
    for (int idx = tid; idx < 16 * DH; idx += 128) {
        int l = idx / DH, d = idx % DH;
        size_t off = (size_t)l * ((size_t)SS * 2304);
        q[l][d] = base[off + d];
        k[l][d] = base[off + 768 + d];
        v[l][d] = base[off + 1536 + d];
    }
    __syncthreads();

    const float scale = rsqrtf((float)DH);
    for (int idx = tid; idx < 256; idx += 128) {
        int l = idx >> 4, m = idx & 15;
        float acc = 0.0f;
#pragma unroll
        for (int d = 0; d < DH; d++) acc = fmaf(q[l][d], k[m][d], acc);
        sc[l][m] = acc * scale;
    }
    __syncthreads();

    if (tid < 16) {
        float mx = -INFINITY;
#pragma unroll
        for (int m = 0; m < 16; m++) mx = fmaxf(mx, sc[tid][m]);
        float sum = 0.0f;
#pragma unroll
        for (int m = 0; m < 16; m++) {
            float e = expf(sc[tid][m] - mx);
            sc[tid][m] = e;
            sum += e;
        }
        float inv = 1.0f / sum;
#pragma unroll
        for (int m = 0; m < 16; m++) sc[tid][m] *= inv;
    }
    __syncthreads();

    for (int idx = tid; idx < 16 * DH; idx += 128) {
        int l = idx / DH, d = idx % DH;
        float acc = 0.0f;
#pragma unroll
        for (int m = 0; m < 16; m++) acc = fmaf(sc[l][m], v[m][d], acc);
        g_ctx[((size_t)l * SS + s) * EE + h * DH + d] = acc;
    }
}

// ---------------------------------------------------------------------------
// prob = h @ w2^T + b2, then broadcast row: out[r, :] = prob[r]
// grid = 32768 blocks, 256 threads.
// ---------------------------------------------------------------------------
__global__ __launch_bounds__(256)
void prob_bcast(const float* __restrict__ hbuf, const float* __restrict__ w2,
                const float* __restrict__ b2, float* __restrict__ out) {
    const int r = blockIdx.x;
    const int tid = threadIdx.x;

    float p = 0.0f;
    for (int j = tid; j < 384; j += 256)
        p = fmaf(hbuf[(size_t)r * 384 + j], w2[j], p);

    __shared__ float red[256];
    red[tid] = p;
    __syncthreads();
#pragma unroll
    for (int st = 128; st > 0; st >>= 1) {
        if (tid < st) red[tid] += red[tid + st];
        __syncthreads();
    }
    __shared__ float probsh;
    if (tid == 0) probsh = red[0] + b2[0];
    __syncthreads();

    float pv = probsh;
    float4 pv4 = make_float4(pv, pv, pv, pv);
    float4* orow = (float4*)(out + (size_t)r * SS);
#pragma unroll
    for (int c = tid; c < SS / 4; c += 256) orow[c] = pv4;
}

// ---------------------------------------------------------------------------
extern "C" void kernel_launch(void* const* d_in, const int* in_sizes, int n_in,
                              void* d_out, int out_size) {
    const float* features = (const float*)d_in[0];
    const float* in_w     = (const float*)d_in[1];
    const float* in_b     = (const float*)d_in[2];
    const float* out_w    = (const float*)d_in[3];
    const float* out_b    = (const float*)d_in[4];
    const float* w1       = (const float*)d_in[5];
    const float* b1       = (const float*)d_in[6];
    const float* w2       = (const float*)d_in[7];
    const float* b2       = (const float*)d_in[8];
    float* out = (float*)d_out;

    float *qkv, *ctx, *att, *hb;
    cudaGetSymbolAddress((void**)&qkv, g_qkv);
    cudaGetSymbolAddress((void**)&ctx, g_ctx);
    cudaGetSymbolAddress((void**)&att, g_att);
    cudaGetSymbolAddress((void**)&hb,  g_h);

    // 1) qkv = features @ in_proj_w^T + b   (32768 x 2304, K=768)
    gemm_nt<0><<<dim3(2304 / 128, MM / 128), 256>>>(features, in_w, in_b, qkv, 2304, 768);

    // 2) attention over axis-0 per (s,h) -> ctx (32768 x 768)
    attn_kernel<<<dim3(SS, HH), 128>>>();

    // 3) attn_out = ctx @ out_proj_w^T + b  (32768 x 768, K=768)
    gemm_nt<0><<<dim3(768 / 128, MM / 128), 256>>>(ctx, out_w, out_b, att, 768, 768);

    // 4) h = relu(attn_out @ w1^T + b1)     (32768 x 384, K=768)
    gemm_nt<1><<<dim3(384 / 128, MM / 128), 256>>>(att, w1, b1, hb, 384, 768);

    // 5) prob + broadcast to (16, 2048, 2048)
    prob_bcast<<<MM, 256>>>(hb, w2, b2, out);
}

// round 3
// speedup vs baseline: 2.4406x; 2.4406x over previous
#include <cuda_runtime.h>
#include <cuda_bf16.h>
#include <math.h>
#include <stdint.h>

#define BBATCH 16
#define SSEQ   2048
#define EMB    768
#define NHEAD  8
#define DHEAD  96
#define MROWS  (BBATCH*SSEQ)   // 32768
#define KDIM   768

// ---------------- scratch (device globals; allocation-free rule) -----------
__device__ float          g_qkv[(size_t)MROWS*2304];
__device__ __nv_bfloat16  g_fhi[(size_t)MROWS*KDIM];
__device__ __nv_bfloat16  g_flo[(size_t)MROWS*KDIM];
__device__ __nv_bfloat16  g_chi[(size_t)MROWS*KDIM];
__device__ __nv_bfloat16  g_clo[(size_t)MROWS*KDIM];
__device__ __nv_bfloat16  g_ohi[(size_t)MROWS*KDIM];
__device__ __nv_bfloat16  g_olo[(size_t)MROWS*KDIM];
__device__ float          g_hbuf[(size_t)MROWS*384];
__device__ __nv_bfloat16  g_whi[(size_t)(2304+768+384)*KDIM];
__device__ __nv_bfloat16  g_wlo[(size_t)(2304+768+384)*KDIM];

// ---------------- helpers ---------------------------------------------------
__device__ __forceinline__ uint32_t s2u(const void* p){
    uint32_t a;
    asm("{ .reg .u64 t; cvta.to.shared.u64 t, %1; cvt.u32.u64 %0, t; }":"=r"(a):"l"(p));
    return a;
}
#define SWZ(o) ((o) ^ (((o) >> 3) & 0x70))
#define CP16(s, g) asm volatile("cp.async.cg.shared.global [%0], [%1], 16;"::"r"(s),"l"(g):"memory")

// ---------------- fp32 -> bf16 hi/lo split (vectorized x4) -----------------
__global__ __launch_bounds__(256)
void split4(const float* __restrict__ src, __nv_bfloat16* __restrict__ hi,
            __nv_bfloat16* __restrict__ lo, size_t n4){
    size_t i = (size_t)blockIdx.x * blockDim.x + threadIdx.x;
    if (i >= n4) return;
    float4 v = ((const float4*)src)[i];
    __nv_bfloat16 h0=__float2bfloat16(v.x), h1=__float2bfloat16(v.y),
                  h2=__float2bfloat16(v.z), h3=__float2bfloat16(v.w);
    __nv_bfloat16 l0=__float2bfloat16(v.x-__bfloat162float(h0)),
                  l1=__float2bfloat16(v.y-__bfloat162float(h1)),
                  l2=__float2bfloat16(v.z-__bfloat162float(h2)),
                  l3=__float2bfloat16(v.w-__bfloat162float(h3));
    ((__nv_bfloat162*)hi)[2*i]   = __nv_bfloat162(h0,h1);
    ((__nv_bfloat162*)hi)[2*i+1] = __nv_bfloat162(h2,h3);
    ((__nv_bfloat162*)lo)[2*i]   = __nv_bfloat162(l0,l1);
    ((__nv_bfloat162*)lo)[2*i+1] = __nv_bfloat162(l2,l3);
}

// ---------------- mma.sync GEMM: C[M x N] = A @ B^T + bias -----------------
// 3-pass hi/lo split: Ahi*Bhi + Alo*Bhi + Ahi*Blo, fp32 accumulate.
// CTA tile 128x128, BK=64, double-buffered cp.async, 8 warps (2M x 4N),
// warp tile 64x32 via m16n8k16.
// EPI: 0 = fp32 out, 1 = fp32+ReLU, 2 = bf16 hi/lo planes out.
template<int EPI>
__global__ __launch_bounds__(256, 2)
void gemm_mma(const __nv_bfloat16* __restrict__ Ahi, const __nv_bfloat16* __restrict__ Alo,
              const __nv_bfloat16* __restrict__ Bhi, const __nv_bfloat16* __restrict__ Blo,
              const float* __restrict__ bias, float* __restrict__ Cf,
              __nv_bfloat16* __restrict__ Chi, __nv_bfloat16* __restrict__ Clo, int N)
{
    extern __shared__ __align__(1024) char sm[];
    constexpr int NIT = 36;                 // 3 passes x 12 chunks of K=64
    const int tid = threadIdx.x, lane = tid & 31, warp = tid >> 5;
    const int m0 = blockIdx.y * 128, n0 = blockIdx.x * 128;
    const int wm = (warp & 1) * 64, wn = (warp >> 1) * 32;
    const uint32_t sbase = s2u(sm);

    auto load_tile = [&](int t){
        const int b = t & 1;
        const __nv_bfloat16* Ap = (t < 12) ? Ahi : ((t < 24) ? Alo : Ahi);
        const __nv_bfloat16* Bp = (t < 24) ? Bhi : Blo;
        const int kbase = (t % 12) * 64;
        const uint32_t sA = sbase + b * 32768u;
        const uint32_t sB = sA + 16384u;
        #pragma unroll
        for (int i = 0; i < 4; i++){
            int g = tid + i * 256;
            int row = g >> 3, sl = g & 7;
            uint32_t d = SWZ((uint32_t)(row * 128 + sl * 16));
            CP16(sA + d, Ap + (size_t)(m0 + row) * KDIM + kbase + sl * 8);
            CP16(sB + d, Bp + (size_t)(n0 + row) * KDIM + kbase + sl * 8);
        }
        asm volatile("cp.async.commit_group;" ::: "memory");
    };

    float acc[4][4][4];
    #pragma unroll
    for (int mi = 0; mi < 4; mi++)
        #pragma unroll
        for (int ni = 0; ni < 4; ni++)
            #pragma unroll
            for (int r = 0; r < 4; r++) acc[mi][ni][r] = 0.0f;

    load_tile(0);
    load_tile(1);

    const int      aRow   = lane & 15;
    const uint32_t aCol   = (uint32_t)(lane >> 4) * 16u;
    const int      bRow   = lane & 7;
    const uint32_t bCol   = (uint32_t)((lane >> 3) & 1) * 16u;

    #pragma unroll 1
    for (int t = 0; t < NIT; t++){
        if (t < NIT - 2) asm volatile("cp.async.wait_group 1;" ::: "memory");
        else             asm volatile("cp.async.wait_group 0;" ::: "memory");
        __syncthreads();

        const uint32_t sA = sbase + (uint32_t)(t & 1) * 32768u;
        const uint32_t sB = sA + 16384u;

        #pragma unroll
        for (int kk = 0; kk < 4; kk++){
            const uint32_t kb = (uint32_t)kk * 32u;     // kstep byte offset
            uint32_t a[4][4], bf[4][2];
            #pragma unroll
            for (int mi = 0; mi < 4; mi++){
                uint32_t off = (uint32_t)((wm + mi * 16 + aRow) * 128) + kb + aCol;
                uint32_t ad = sA + SWZ(off);
                asm volatile("ldmatrix.sync.aligned.m8n8.x4.shared.b16 {%0,%1,%2,%3},[%4];"
                    : "=r"(a[mi][0]), "=r"(a[mi][1]), "=r"(a[mi][2]), "=r"(a[mi][3]) : "r"(ad));
            }
            #pragma unroll
            for (int ni = 0; ni < 4; ni++){
                uint32_t off = (uint32_t)((wn + ni * 8 + bRow) * 128) + kb + bCol;
                uint32_t bd = sB + SWZ(off);
                asm volatile("ldmatrix.sync.aligned.m8n8.x2.shared.b16 {%0,%1},[%2];"
                    : "=r"(bf[ni][0]), "=r"(bf[ni][1]) : "r"(bd));
            }
            #pragma unroll
            for (int mi = 0; mi < 4; mi++)
                #pragma unroll
                for (int ni = 0; ni < 4; ni++)
                    asm volatile("mma.sync.aligned.m16n8k16.row.col.f32.bf16.bf16.f32 "
                        "{%0,%1,%2,%3},{%4,%5,%6,%7},{%8,%9},{%0,%1,%2,%3};"
                        : "+f"(acc[mi][ni][0]), "+f"(acc[mi][ni][1]),
                          "+f"(acc[mi][ni][2]), "+f"(acc[mi][ni][3])
                        : "r"(a[mi][0]), "r"(a[mi][1]), "r"(a[mi][2]), "r"(a[mi][3]),
                          "r"(bf[ni][0]), "r"(bf[ni][1]));
        }
        __syncthreads();
        if (t + 2 < NIT) load_tile(t + 2);
    }

    // ---------------- epilogue ----------------
    const int erow = lane >> 2;           // 0..7
    const int ecol = (lane & 3) * 2;      // 0,2,4,6
    #pragma unroll
    for (int mi = 0; mi < 4; mi++){
        #pragma unroll
        for (int ni = 0; ni < 4; ni++){
            const int row = m0 + wm + mi * 16 + erow;
            const int col = n0 + wn + ni * 8 + ecol;
            const float b0 = bias[col], b1 = bias[col + 1];
            float v0 = acc[mi][ni][0] + b0, v1 = acc[mi][ni][1] + b1;
            float v2 = acc[mi][ni][2] + b0, v3 = acc[mi][ni][3] + b1;
            if (EPI == 1){
                v0 = fmaxf(v0, 0.f); v1 = fmaxf(v1, 0.f);
                v2 = fmaxf(v2, 0.f); v3 = fmaxf(v3, 0.f);
            }
            if (EPI == 2){
                __nv_bfloat16 h0 = __float2bfloat16(v0), h1 = __float2bfloat16(v1);
                __nv_bfloat16 h2 = __float2bfloat16(v2), h3 = __float2bfloat16(v3);
                __nv_bfloat16 l0 = __float2bfloat16(v0 - __bfloat162float(h0));
                __nv_bfloat16 l1 = __float2bfloat16(v1 - __bfloat162float(h1));
                __nv_bfloat16 l2 = __float2bfloat16(v2 - __bfloat162float(h2));
                __nv_bfloat16 l3 = __float2bfloat16(v3 - __bfloat162float(h3));
                *(__nv_bfloat162*)(Chi + (size_t)row * N + col)       = __nv_bfloat162(h0, h1);
                *(__nv_bfloat162*)(Clo + (size_t)row * N + col)       = __nv_bfloat162(l0, l1);
                *(__nv_bfloat162*)(Chi + (size_t)(row + 8) * N + col) = __nv_bfloat162(h2, h3);
                *(__nv_bfloat162*)(Clo + (size_t)(row + 8) * N + col) = __nv_bfloat162(l2, l3);
            } else {
                *(float2*)(Cf + (size_t)row * N + col)       = make_float2(v0, v1);
                *(float2*)(Cf + (size_t)(row + 8) * N + col) = make_float2(v2, v3);
            }
        }
    }
}

// ---------------- attention over axis-0 (16) per (s,h) ---------------------
__global__ __launch_bounds__(128)
void attn_kernel(){
    const int s = blockIdx.x, h = blockIdx.y, tid = threadIdx.x;
    __shared__ float q[16][96], k[16][96], v[16][96], sc[16][17];

    const float* base = g_qkv + (size_t)s*2304 + h*DHEAD;
    for (int idx = tid; idx < 16*DHEAD; idx += 128){
        int l = idx / DHEAD, d = idx % DHEAD;
        size_t off = (size_t)l * ((size_t)SSEQ * 2304);
        q[l][d] = base[off + d];
        k[l][d] = base[off + 768 + d];
        v[l][d] = base[off + 1536 + d];
    }
    __syncthreads();

    const float scale = rsqrtf((float)DHEAD);
    for (int idx = tid; idx < 256; idx += 128){
        int l = idx >> 4, m = idx & 15;
        float acc = 0.f;
        #pragma unroll
        for (int d = 0; d < DHEAD; d++) acc = fmaf(q[l][d], k[m][d], acc);
        sc[l][m] = acc * scale;
    }
    __syncthreads();

    if (tid < 16){
        float mx = -INFINITY;
        #pragma unroll
        for (int m = 0; m < 16; m++) mx = fmaxf(mx, sc[tid][m]);
        float sum = 0.f;
        #pragma unroll
        for (int m = 0; m < 16; m++){ float e = expf(sc[tid][m]-mx); sc[tid][m]=e; sum+=e; }
        float inv = 1.f/sum;
        #pragma unroll
        for (int m = 0; m < 16; m++) sc[tid][m] *= inv;
    }
    __syncthreads();

    for (int idx = tid; idx < 16*DHEAD; idx += 128){
        int l = idx / DHEAD, d = idx % DHEAD;
        float acc = 0.f;
        #pragma unroll
        for (int m = 0; m < 16; m++) acc = fmaf(sc[l][m], v[m][d], acc);
        size_t o = ((size_t)l*SSEQ + s)*EMB + h*DHEAD + d;
        __nv_bfloat16 hh = __float2bfloat16(acc);
        g_chi[o] = hh;
        g_clo[o] = __float2bfloat16(acc - __bfloat162float(hh));
    }
}

// ---------------- prob + broadcast -----------------------------------------
__global__ __launch_bounds__(256)
void prob_bcast(const float* __restrict__ hbuf, const float* __restrict__ w2,
                const float* __restrict__ b2, float* __restrict__ out){
    const int r = blockIdx.x, tid = threadIdx.x;
    float p = 0.f;
    for (int j = tid; j < 384; j += 256)
        p = fmaf(hbuf[(size_t)r*384 + j], w2[j], p);
    __shared__ float red[256];
    red[tid] = p; __syncthreads();
    #pragma unroll
    for (int st = 128; st > 0; st >>= 1){
        if (tid < st) red[tid] += red[tid+st];
        __syncthreads();
    }
    __shared__ float probsh;
    if (tid == 0) probsh = red[0] + b2[0];
    __syncthreads();
    float4 pv4 = make_float4(probsh, probsh, probsh, probsh);
    float4* orow = (float4*)(out + (size_t)r*SSEQ);
    for (int c = tid; c < SSEQ/4; c += 256) orow[c] = pv4;
}

// ---------------------------------------------------------------------------
extern "C" void kernel_launch(void* const* d_in, const int* in_sizes, int n_in,
                              void* d_out, int out_size){
    const float* features = (const float*)d_in[0];
    const float* in_w  = (const float*)d_in[1];
    const float* in_b  = (const float*)d_in[2];
    const float* out_w = (const float*)d_in[3];
    const float* out_b = (const float*)d_in[4];
    const float* w1    = (const float*)d_in[5];
    const float* b1    = (const float*)d_in[6];
    const float* w2    = (const float*)d_in[7];
    const float* b2    = (const float*)d_in[8];
    float* out = (float*)d_out;

    float *qkv, *hb;
    __nv_bfloat16 *fhi,*flo,*chi,*clo,*ohi,*olo,*whi,*wlo;
    cudaGetSymbolAddress((void**)&qkv, g_qkv);
    cudaGetSymbolAddress((void**)&hb,  g_hbuf);
    cudaGetSymbolAddress((void**)&fhi, g_fhi);
    cudaGetSymbolAddress((void**)&flo, g_flo);
    cudaGetSymbolAddress((void**)&chi, g_chi);
    cudaGetSymbolAddress((void**)&clo, g_clo);
    cudaGetSymbolAddress((void**)&ohi, g_ohi);
    cudaGetSymbolAddress((void**)&olo, g_olo);
    cudaGetSymbolAddress((void**)&whi, g_whi);
    cudaGetSymbolAddress((void**)&wlo, g_wlo);

    const size_t OFF_OW = (size_t)2304*KDIM;
    const size_t OFF_W1 = (size_t)(2304+768)*KDIM;

    const int SMEM = 2 * 32768;   // 64 KB double buffer
    cudaFuncSetAttribute(gemm_mma<0>, cudaFuncAttributeMaxDynamicSharedMemorySize, SMEM);
    cudaFuncSetAttribute(gemm_mma<1>, cudaFuncAttributeMaxDynamicSharedMemorySize, SMEM);
    cudaFuncSetAttribute(gemm_mma<2>, cudaFuncAttributeMaxDynamicSharedMemorySize, SMEM);

    // split inputs into bf16 hi/lo planes
    {
        size_t n4 = (size_t)MROWS*KDIM/4;
        split4<<<(unsigned)((n4+255)/256), 256>>>(features, fhi, flo, n4);
        n4 = (size_t)2304*KDIM/4;
        split4<<<(unsigned)((n4+255)/256), 256>>>(in_w, whi, wlo, n4);
        n4 = (size_t)768*KDIM/4;
        split4<<<(unsigned)((n4+255)/256), 256>>>(out_w, whi+OFF_OW, wlo+OFF_OW, n4);
        n4 = (size_t)384*KDIM/4;
        split4<<<(unsigned)((n4+255)/256), 256>>>(w1, whi+OFF_W1, wlo+OFF_W1, n4);
    }

    // 1) qkv = features @ in_w^T + in_b          (32768 x 2304)
    gemm_mma<0><<<dim3(2304/128, MROWS/128), 256, SMEM>>>(
        fhi, flo, whi, wlo, in_b, qkv, nullptr, nullptr, 2304);

    // 2) attention -> ctx hi/lo planes
    attn_kernel<<<dim3(SSEQ, NHEAD), 128>>>();

    // 3) att = ctx @ out_w^T + out_b -> hi/lo planes   (32768 x 768)
    gemm_mma<2><<<dim3(768/128, MROWS/128), 256, SMEM>>>(
        chi, clo, whi+OFF_OW, wlo+OFF_OW, out_b, nullptr, ohi, olo, 768);

    // 4) h = relu(att @ w1^T + b1)               (32768 x 384)
    gemm_mma<1><<<dim3(384/128, MROWS/128), 256, SMEM>>>(
        ohi, olo, whi+OFF_W1, wlo+OFF_W1, b1, hb, nullptr, nullptr, 384);

    // 5) prob + broadcast
    prob_bcast<<<MROWS, 256>>>(hb, w2, b2, out);
}

// round 4
// speedup vs baseline: 2.5591x; 1.0486x over previous
#include <cuda_runtime.h>
#include <cuda_bf16.h>
#include <math.h>
#include <stdint.h>

#define BBATCH 16
#define SSEQ   2048
#define EMB    768
#define NHEAD  8
#define DHEAD  96
#define MROWS  (BBATCH*SSEQ)   // 32768
#define KDIM   768
#define NCH    24              // 768 / BK, BK=32

// ---------------- scratch (device globals; allocation-free rule) -----------
__device__ float          g_qkv[(size_t)MROWS*2304];
__device__ __nv_bfloat16  g_fhi[(size_t)MROWS*KDIM];
__device__ __nv_bfloat16  g_flo[(size_t)MROWS*KDIM];
__device__ __nv_bfloat16  g_chi[(size_t)MROWS*KDIM];
__device__ __nv_bfloat16  g_clo[(size_t)MROWS*KDIM];
__device__ __nv_bfloat16  g_ohi[(size_t)MROWS*KDIM];
__device__ __nv_bfloat16  g_olo[(size_t)MROWS*KDIM];
__device__ float          g_hbuf[(size_t)MROWS*384];
__device__ __nv_bfloat16  g_whi[(size_t)(2304+768+384)*KDIM];
__device__ __nv_bfloat16  g_wlo[(size_t)(2304+768+384)*KDIM];

// ---------------- helpers ---------------------------------------------------
__device__ __forceinline__ uint32_t s2u(const void* p){
    uint32_t a;
    asm("{ .reg .u64 t; cvta.to.shared.u64 t, %1; cvt.u32.u64 %0, t; }":"=r"(a):"l"(p));
    return a;
}
#define SWZ(o) ((o) ^ (((o) >> 3) & 0x70))
#define CP16(s, g) asm volatile("cp.async.cg.shared.global [%0], [%1], 16;"::"r"(s),"l"(g):"memory")

__device__ __forceinline__ void mma16816(float* c, const uint32_t* a, uint32_t b0, uint32_t b1){
    asm volatile("mma.sync.aligned.m16n8k16.row.col.f32.bf16.bf16.f32 "
        "{%0,%1,%2,%3},{%4,%5,%6,%7},{%8,%9},{%0,%1,%2,%3};"
        : "+f"(c[0]), "+f"(c[1]), "+f"(c[2]), "+f"(c[3])
        : "r"(a[0]), "r"(a[1]), "r"(a[2]), "r"(a[3]), "r"(b0), "r"(b1));
}

// ---------------- fp32 -> bf16 hi/lo split (vectorized x4) -----------------
__global__ __launch_bounds__(256)
void split4(const float* __restrict__ src, __nv_bfloat16* __restrict__ hi,
            __nv_bfloat16* __restrict__ lo, size_t n4){
    size_t i = (size_t)blockIdx.x * blockDim.x + threadIdx.x;
    if (i >= n4) return;
    float4 v = ((const float4*)src)[i];
    __nv_bfloat16 h0=__float2bfloat16(v.x), h1=__float2bfloat16(v.y),
                  h2=__float2bfloat16(v.z), h3=__float2bfloat16(v.w);
    __nv_bfloat16 l0=__float2bfloat16(v.x-__bfloat162float(h0)),
                  l1=__float2bfloat16(v.y-__bfloat162float(h1)),
                  l2=__float2bfloat16(v.z-__bfloat162float(h2)),
                  l3=__float2bfloat16(v.w-__bfloat162float(h3));
    ((__nv_bfloat162*)hi)[2*i]   = __nv_bfloat162(h0,h1);
    ((__nv_bfloat162*)hi)[2*i+1] = __nv_bfloat162(h2,h3);
    ((__nv_bfloat162*)lo)[2*i]   = __nv_bfloat162(l0,l1);
    ((__nv_bfloat162*)lo)[2*i+1] = __nv_bfloat162(l2,l3);
}

// ---------------- mma.sync GEMM with shared-load 3-pass hi/lo split --------
// CTA 128x128, BK=32. Smem row = [hi 64B | lo 64B] (SW128). 3-stage ring.
// Per kstep: load Ahi,Bhi,Blo frags -> P1 (hh), P3 (hl), reload A with lo
// (register reuse) -> P2 (lh). EPI: 0 fp32, 1 fp32+ReLU, 2 bf16 hi/lo out.
template<int EPI>
__global__ __launch_bounds__(256, 2)
void gemm_mma(const __nv_bfloat16* __restrict__ Ahi, const __nv_bfloat16* __restrict__ Alo,
              const __nv_bfloat16* __restrict__ Bhi, const __nv_bfloat16* __restrict__ Blo,
              const float* __restrict__ bias, float* __restrict__ Cf,
              __nv_bfloat16* __restrict__ Chi, __nv_bfloat16* __restrict__ Clo, int N)
{
    extern __shared__ __align__(1024) char sm[];
    const int tid = threadIdx.x, lane = tid & 31, warp = tid >> 5;
    const int m0 = blockIdx.y * 128, n0 = blockIdx.x * 128;
    const int wm = (warp & 1) * 64, wn = (warp >> 1) * 32;
    const uint32_t sbase = s2u(sm);

    auto load_tile = [&](int t){
        const uint32_t st = sbase + (uint32_t)(t % 3) * 32768u;
        const int k0 = t * 32;
        #pragma unroll
        for (int i = 0; i < 4; i++){                  // A granules
            int g = tid + i * 256;
            int row = g >> 3, slot = g & 7;
            int pl = slot >> 2, gg = slot & 3;
            uint32_t d = SWZ((uint32_t)(row * 128 + pl * 64 + gg * 16));
            const __nv_bfloat16* src = (pl ? Alo : Ahi) + (size_t)(m0 + row) * KDIM + k0 + gg * 8;
            CP16(st + d, src);
        }
        #pragma unroll
        for (int i = 0; i < 4; i++){                  // B granules
            int g = tid + i * 256;
            int row = g >> 3, slot = g & 7;
            int pl = slot >> 2, gg = slot & 3;
            uint32_t d = SWZ((uint32_t)(16384u + row * 128 + pl * 64 + gg * 16));
            const __nv_bfloat16* src = (pl ? Blo : Bhi) + (size_t)(n0 + row) * KDIM + k0 + gg * 8;
            CP16(st + d, src);
        }
        asm volatile("cp.async.commit_group;" ::: "memory");
    };

    float acc[4][4][4];
    #pragma unroll
    for (int mi = 0; mi < 4; mi++)
        #pragma unroll
        for (int ni = 0; ni < 4; ni++)
            #pragma unroll
            for (int r = 0; r < 4; r++) acc[mi][ni][r] = 0.0f;

    load_tile(0);
    load_tile(1);

    const uint32_t aRow = (uint32_t)(lane & 15);
    const uint32_t aCol = (uint32_t)(lane >> 4) * 16u;
    const uint32_t bRow = (uint32_t)(((lane >> 4) & 1) * 8 + (lane & 7));
    const uint32_t bCol = (uint32_t)((lane >> 3) & 1) * 16u;

    #pragma unroll 1
    for (int t = 0; t < NCH; t++){
        if (t < NCH - 1) asm volatile("cp.async.wait_group 1;" ::: "memory");
        else             asm volatile("cp.async.wait_group 0;" ::: "memory");
        __syncthreads();

        const uint32_t sA = sbase + (uint32_t)(t % 3) * 32768u;
        const uint32_t sB = sA + 16384u;

        #pragma unroll
        for (int kk = 0; kk < 2; kk++){
            const uint32_t kb = (uint32_t)kk * 32u;
            uint32_t a[4][4], bh[8], bl[8];

            #pragma unroll
            for (int np = 0; np < 2; np++){           // B hi: 2 x LDSM.x4
                uint32_t ad = sB + SWZ((uint32_t)((wn + np*16 + bRow) * 128) + kb + bCol);
                asm volatile("ldmatrix.sync.aligned.m8n8.x4.shared.b16 {%0,%1,%2,%3},[%4];"
                    : "=r"(bh[np*4]), "=r"(bh[np*4+1]), "=r"(bh[np*4+2]), "=r"(bh[np*4+3]) : "r"(ad));
            }
            #pragma unroll
            for (int np = 0; np < 2; np++){           // B lo
                uint32_t ad = sB + SWZ((uint32_t)((wn + np*16 + bRow) * 128) + 64u + kb + bCol);
                asm volatile("ldmatrix.sync.aligned.m8n8.x4.shared.b16 {%0,%1,%2,%3},[%4];"
                    : "=r"(bl[np*4]), "=r"(bl[np*4+1]), "=r"(bl[np*4+2]), "=r"(bl[np*4+3]) : "r"(ad));
            }
            #pragma unroll
            for (int mi = 0; mi < 4; mi++){           // A hi
                uint32_t ad = sA + SWZ((uint32_t)((wm + mi*16 + aRow) * 128) + kb + aCol);
                asm volatile("ldmatrix.sync.aligned.m8n8.x4.shared.b16 {%0,%1,%2,%3},[%4];"
                    : "=r"(a[mi][0]), "=r"(a[mi][1]), "=r"(a[mi][2]), "=r"(a[mi][3]) : "r"(ad));
            }
            // P1 (hi*hi) + P3 (hi*lo)
            #pragma unroll
            for (int mi = 0; mi < 4; mi++)
                #pragma unroll
                for (int ni = 0; ni < 4; ni++){
                    mma16816(acc[mi][ni], a[mi], bh[(ni>>1)*4 + (ni&1)*2], bh[(ni>>1)*4 + (ni&1)*2 + 1]);
                    mma16816(acc[mi][ni], a[mi], bl[(ni>>1)*4 + (ni&1)*2], bl[(ni>>1)*4 + (ni&1)*2 + 1]);
                }
            #pragma unroll
            for (int mi = 0; mi < 4; mi++){           // A lo (reuse a regs)
                uint32_t ad = sA + SWZ((uint32_t)((wm + mi*16 + aRow) * 128) + 64u + kb + aCol);
                asm volatile("ldmatrix.sync.aligned.m8n8.x4.shared.b16 {%0,%1,%2,%3},[%4];"
                    : "=r"(a[mi][0]), "=r"(a[mi][1]), "=r"(a[mi][2]), "=r"(a[mi][3]) : "r"(ad));
            }
            // P2 (lo*hi)
            #pragma unroll
            for (int mi = 0; mi < 4; mi++)
                #pragma unroll
                for (int ni = 0; ni < 4; ni++)
                    mma16816(acc[mi][ni], a[mi], bh[(ni>>1)*4 + (ni&1)*2], bh[(ni>>1)*4 + (ni&1)*2 + 1]);
        }
        if (t + 2 < NCH) load_tile(t + 2);
    }

    // ---------------- epilogue ----------------
    const int erow = lane >> 2;
    const int ecol = (lane & 3) * 2;
    #pragma unroll
    for (int mi = 0; mi < 4; mi++){
        #pragma unroll
        for (int ni = 0; ni < 4; ni++){
            const int row = m0 + wm + mi * 16 + erow;
            const int col = n0 + wn + ni * 8 + ecol;
            const float b0 = bias[col], b1 = bias[col + 1];
            float v0 = acc[mi][ni][0] + b0, v1 = acc[mi][ni][1] + b1;
            float v2 = acc[mi][ni][2] + b0, v3 = acc[mi][ni][3] + b1;
            if (EPI == 1){
                v0 = fmaxf(v0, 0.f); v1 = fmaxf(v1, 0.f);
                v2 = fmaxf(v2, 0.f); v3 = fmaxf(v3, 0.f);
            }
            if (EPI == 2){
                __nv_bfloat16 h0 = __float2bfloat16(v0), h1 = __float2bfloat16(v1);
                __nv_bfloat16 h2 = __float2bfloat16(v2), h3 = __float2bfloat16(v3);
                __nv_bfloat16 l0 = __float2bfloat16(v0 - __bfloat162float(h0));
                __nv_bfloat16 l1 = __float2bfloat16(v1 - __bfloat162float(h1));
                __nv_bfloat16 l2 = __float2bfloat16(v2 - __bfloat162float(h2));
                __nv_bfloat16 l3 = __float2bfloat16(v3 - __bfloat162float(h3));
                *(__nv_bfloat162*)(Chi + (size_t)row * N + col)       = __nv_bfloat162(h0, h1);
                *(__nv_bfloat162*)(Clo + (size_t)row * N + col)       = __nv_bfloat162(l0, l1);
                *(__nv_bfloat162*)(Chi + (size_t)(row + 8) * N + col) = __nv_bfloat162(h2, h3);
                *(__nv_bfloat162*)(Clo + (size_t)(row + 8) * N + col) = __nv_bfloat162(l2, l3);
            } else {
                *(float2*)(Cf + (size_t)row * N + col)       = make_float2(v0, v1);
                *(float2*)(Cf + (size_t)(row + 8) * N + col) = make_float2(v2, v3);
            }
        }
    }
}

// ---------------- attention over axis-0 (16) per (s,h) ---------------------
__global__ __launch_bounds__(128)
void attn_kernel(){
    const int s = blockIdx.x, h = blockIdx.y, tid = threadIdx.x;
    __shared__ float q[16][96], k[16][96], v[16][96], sc[16][17];

    const float* base = g_qkv + (size_t)s*2304 + h*DHEAD;
    for (int idx = tid; idx < 16*DHEAD; idx += 128){
        int l = idx / DHEAD, d = idx % DHEAD;
        size_t off = (size_t)l * ((size_t)SSEQ * 2304);
        q[l][d] = base[off + d];
        k[l][d] = base[off + 768 + d];
        v[l][d] = base[off + 1536 + d];
    }
    __syncthreads();

    const float scale = rsqrtf((float)DHEAD);
    for (int idx = tid; idx < 256; idx += 128){
        int l = idx >> 4, m = idx & 15;
        float acc = 0.f;
        #pragma unroll
        for (int d = 0; d < DHEAD; d++) acc = fmaf(q[l][d], k[m][d], acc);
        sc[l][m] = acc * scale;
    }
    __syncthreads();

    if (tid < 16){
        float mx = -INFINITY;
        #pragma unroll
        for (int m = 0; m < 16; m++) mx = fmaxf(mx, sc[tid][m]);
        float sum = 0.f;
        #pragma unroll
        for (int m = 0; m < 16; m++){ float e = expf(sc[tid][m]-mx); sc[tid][m]=e; sum+=e; }
        float inv = 1.f/sum;
        #pragma unroll
        for (int m = 0; m < 16; m++) sc[tid][m] *= inv;
    }
    __syncthreads();

    for (int idx = tid; idx < 16*DHEAD; idx += 128){
        int l = idx / DHEAD, d = idx % DHEAD;
        float acc = 0.f;
        #pragma unroll
        for (int m = 0; m < 16; m++) acc = fmaf(sc[l][m], v[m][d], acc);
        size_t o = ((size_t)l*SSEQ + s)*EMB + h*DHEAD + d;
        __nv_bfloat16 hh = __float2bfloat16(acc);
        g_chi[o] = hh;
        g_clo[o] = __float2bfloat16(acc - __bfloat162float(hh));
    }
}

// ---------------- prob + broadcast -----------------------------------------
__global__ __launch_bounds__(256)
void prob_bcast(const float* __restrict__ hbuf, const float* __restrict__ w2,
                const float* __restrict__ b2, float* __restrict__ out){
    const int r = blockIdx.x, tid = threadIdx.x;
    float p = 0.f;
    for (int j = tid; j < 384; j += 256)
        p = fmaf(hbuf[(size_t)r*384 + j], w2[j], p);
    __shared__ float red[256];
    red[tid] = p; __syncthreads();
    #pragma unroll
    for (int st = 128; st > 0; st >>= 1){
        if (tid < st) red[tid] += red[tid+st];
        __syncthreads();
    }
    __shared__ float probsh;
    if (tid == 0) probsh = red[0] + b2[0];
    __syncthreads();
    float4 pv4 = make_float4(probsh, probsh, probsh, probsh);
    float4* orow = (float4*)(out + (size_t)r*SSEQ);
    for (int c = tid; c < SSEQ/4; c += 256) orow[c] = pv4;
}

// ---------------------------------------------------------------------------
extern "C" void kernel_launch(void* const* d_in, const int* in_sizes, int n_in,
                              void* d_out, int out_size){
    const float* features = (const float*)d_in[0];
    const float* in_w  = (const float*)d_in[1];
    const float* in_b  = (const float*)d_in[2];
    const float* out_w = (const float*)d_in[3];
    const float* out_b = (const float*)d_in[4];
    const float* w1    = (const float*)d_in[5];
    const float* b1    = (const float*)d_in[6];
    const float* w2    = (const float*)d_in[7];
    const float* b2    = (const float*)d_in[8];
    float* out = (float*)d_out;

    float *qkv, *hb;
    __nv_bfloat16 *fhi,*flo,*chi,*clo,*ohi,*olo,*whi,*wlo;
    cudaGetSymbolAddress((void**)&qkv, g_qkv);
    cudaGetSymbolAddress((void**)&hb,  g_hbuf);
    cudaGetSymbolAddress((void**)&fhi, g_fhi);
    cudaGetSymbolAddress((void**)&flo, g_flo);
    cudaGetSymbolAddress((void**)&chi, g_chi);
    cudaGetSymbolAddress((void**)&clo, g_clo);
    cudaGetSymbolAddress((void**)&ohi, g_ohi);
    cudaGetSymbolAddress((void**)&olo, g_olo);
    cudaGetSymbolAddress((void**)&whi, g_whi);
    cudaGetSymbolAddress((void**)&wlo, g_wlo);

    const size_t OFF_OW = (size_t)2304*KDIM;
    const size_t OFF_W1 = (size_t)(2304+768)*KDIM;

    const int SMEM = 3 * 32768;   // 96 KB, 3-stage ring
    cudaFuncSetAttribute(gemm_mma<0>, cudaFuncAttributeMaxDynamicSharedMemorySize, SMEM);
    cudaFuncSetAttribute(gemm_mma<1>, cudaFuncAttributeMaxDynamicSharedMemorySize, SMEM);
    cudaFuncSetAttribute(gemm_mma<2>, cudaFuncAttributeMaxDynamicSharedMemorySize, SMEM);

    {
        size_t n4 = (size_t)MROWS*KDIM/4;
        split4<<<(unsigned)((n4+255)/256), 256>>>(features, fhi, flo, n4);
        n4 = (size_t)2304*KDIM/4;
        split4<<<(unsigned)((n4+255)/256), 256>>>(in_w, whi, wlo, n4);
        n4 = (size_t)768*KDIM/4;
        split4<<<(unsigned)((n4+255)/256), 256>>>(out_w, whi+OFF_OW, wlo+OFF_OW, n4);
        n4 = (size_t)384*KDIM/4;
        split4<<<(unsigned)((n4+255)/256), 256>>>(w1, whi+OFF_W1, wlo+OFF_W1, n4);
    }

    // 1) qkv = features @ in_w^T + in_b          (32768 x 2304)
    gemm_mma<0><<<dim3(2304/128, MROWS/128), 256, SMEM>>>(
        fhi, flo, whi, wlo, in_b, qkv, nullptr, nullptr, 2304);

    // 2) attention -> ctx hi/lo planes
    attn_kernel<<<dim3(SSEQ, NHEAD), 128>>>();

    // 3) att = ctx @ out_w^T + out_b -> hi/lo planes   (32768 x 768)
    gemm_mma<2><<<dim3(768/128, MROWS/128), 256, SMEM>>>(
        chi, clo, whi+OFF_OW, wlo+OFF_OW, out_b, nullptr, ohi, olo, 768);

    // 4) h = relu(att @ w1^T + b1)               (32768 x 384)
    gemm_mma<1><<<dim3(384/128, MROWS/128), 256, SMEM>>>(
        ohi, olo, whi+OFF_W1, wlo+OFF_W1, b1, hb, nullptr, nullptr, 384);

    // 5) prob + broadcast
    prob_bcast<<<MROWS, 256>>>(hb, w2, b2, out);
}